// round 1
// baseline (speedup 1.0000x reference)
#include <cuda_runtime.h>

// Problem constants
#define D_      64
#define K_      16
#define N_      65536
#define P_      2
#define NOISEF  0.1f                    // 1/BETA
#define LOG2PI_F 1.83787706640934534f

// Scratch (device globals — no allocation allowed)
__device__ double g_C[D_ * D_];
__device__ double g_loss;

// ---------------------------------------------------------------------------
// Kernel 0: zero accumulators (graph replays must be deterministic)
// ---------------------------------------------------------------------------
__global__ void k_zero() {
    int i = blockIdx.x * blockDim.x + threadIdx.x;
    if (i < D_ * D_) g_C[i] = 0.0;
    if (i == 0) g_loss = 0.0;
}

// ---------------------------------------------------------------------------
// Kernel 1: C = x^T x  (64x64), double accumulation in global.
// 128 blocks x 256 threads. Each block: 512 rows, staged 64 rows at a time
// in shared; 4 groups of 64 threads, each group 16 rows, 8x8 register tile
// per thread (LDS:FMA = 1:4, so FFMA-pipe bound, not LDS bound).
// ---------------------------------------------------------------------------
#define XTX_BLOCKS 128
__global__ __launch_bounds__(256) void k_xtx(const float* __restrict__ x) {
    __shared__ float sx[64 * 64];
    const int tid = threadIdx.x;
    const int g   = tid >> 6;          // group 0..3
    const int t   = tid & 63;
    const int ti  = (t >> 3) << 3;     // 8x8 tile coords
    const int tj  = (t & 7) << 3;

    float acc[8][8];
#pragma unroll
    for (int u = 0; u < 8; ++u)
#pragma unroll
        for (int v = 0; v < 8; ++v) acc[u][v] = 0.f;

    const int rows_per_block = N_ / XTX_BLOCKS;   // 512
    const long long base = (long long)blockIdx.x * rows_per_block * D_;

    for (int it = 0; it < rows_per_block; it += 64) {
        const float* src = x + base + (long long)it * D_;
#pragma unroll
        for (int i = 0; i < 16; ++i) sx[tid + 256 * i] = src[tid + 256 * i];
        __syncthreads();

        const float* rb = sx + g * (16 * 64);
#pragma unroll
        for (int rr = 0; rr < 16; ++rr) {
            float xi[8], xj[8];
#pragma unroll
            for (int u = 0; u < 8; ++u) {
                xi[u] = rb[rr * 64 + ti + u];
                xj[u] = rb[rr * 64 + tj + u];
            }
#pragma unroll
            for (int u = 0; u < 8; ++u)
#pragma unroll
                for (int v = 0; v < 8; ++v) acc[u][v] += xi[u] * xj[v];
        }
        __syncthreads();
    }

    // Reduce the 4 groups into sx (reused as 4096-float staging)
    for (int gg = 0; gg < 4; ++gg) {
        if (g == gg) {
#pragma unroll
            for (int u = 0; u < 8; ++u)
#pragma unroll
                for (int v = 0; v < 8; ++v) {
                    int idx = (ti + u) * 64 + tj + v;
                    if (gg == 0) sx[idx] = acc[u][v];
                    else         sx[idx] += acc[u][v];
                }
        }
        __syncthreads();
    }

    for (int i = tid; i < 4096; i += 256)
        atomicAdd(&g_C[i], (double)sx[i]);
}

// ---------------------------------------------------------------------------
// Kernel 2: one block per (a, p) pair (128 blocks x 256 threads).
//  - Gather Wp = W[perm], Cp = C[perm,perm] into shared
//  - S = Wp Wp^T + 0.1 I  (64x64 in shared)
//  - Unnormalized Gauss-Jordan on rows m..63 (pivots on trailing diag):
//    afterwards sS[m+j][i] / sS[m+j][m+j] = A[i][j]  (A = S_mr inv(S_rr))
//  - v_i = S[i][i] - sum_j A[i][j] S[i][m+j]          (rows < m untouched)
//  - Q_i = Cp[i][i] - 2 A_i.Cmr_i + A_i Crr A_i^T     (sum_n diff^2)
//  - pair contribution: sum_i[-.5 log v - .5 log2pi - .5 Q/(v N)] / (P m)
// ---------------------------------------------------------------------------
__global__ __launch_bounds__(256) void k_pairs(const float* __restrict__ W,
                                               const int* __restrict__ perms) {
    __shared__ float sS[D_][D_ + 1];
    __shared__ float sC[D_][D_ + 1];
    __shared__ float sW[D_][K_ + 1];
    __shared__ int   sperm[D_];
    __shared__ float smult[D_];
    __shared__ float swsum[8];

    const int tid = threadIdx.x;
    const int a   = blockIdx.x >> 1;
    const int p   = blockIdx.x & 1;
    const int m   = a + 1;
    const int r   = D_ - m;
    const int* perm = perms + (a * P_ + p) * D_;

    if (tid < D_) sperm[tid] = perm[tid];
    __syncthreads();

    for (int i = tid; i < D_ * K_; i += 256) {
        int row = i >> 4, c = i & 15;
        sW[row][c] = W[sperm[row] * K_ + c];
    }
    for (int i = tid; i < D_ * D_; i += 256) {
        int row = i >> 6, c = i & 63;
        sC[row][c] = (float)g_C[sperm[row] * D_ + sperm[c]];
    }
    __syncthreads();

    for (int i = tid; i < D_ * D_; i += 256) {
        int row = i >> 6, c = i & 63;
        float s = 0.f;
#pragma unroll
        for (int k = 0; k < K_; ++k) s += sW[row][k] * sW[c][k];
        if (row == c) s += NOISEF;
        sS[row][c] = s;
    }
    __syncthreads();

    if (m < D_) {
        // Jordan elimination on rows m..63 (no row normalization => 2 bars/step,
        // no read/write race on the pivot row)
        for (int k = m; k < D_; ++k) {
            if (tid < D_) {
                int row = tid;
                if (row >= m && row != k)
                    smult[row] = sS[row][k] / sS[k][k];
            }
            __syncthreads();
            for (int i = tid; i < D_ * D_; i += 256) {
                int row = i >> 6, c = i & 63;
                if (row >= m && row != k)
                    sS[row][c] -= smult[row] * sS[k][c];
            }
            __syncthreads();
        }
        // Divide solution columns by the (now diagonal) pivots:
        // sS[m+j][i] := A[i][j] for i < m
        for (int i = tid; i < D_ * D_; i += 256) {
            int row = i >> 6, c = i & 63;
            if (row >= m && c < m)
                sS[row][c] /= sS[row][row];
        }
        __syncthreads();
    }

    // Per-warp: v_i, Q_i, log-density term
    const int wid = tid >> 5, lane = tid & 31;
    float wsum = 0.f;
    for (int i = wid; i < m; i += 8) {
        float accv = 0.f, accq1 = 0.f, accq2 = 0.f;
        for (int j = lane; j < r; j += 32) {
            float aij = sS[m + j][i];
            accv  += aij * sS[i][m + j];
            accq1 += aij * sC[i][m + j];
            float u = 0.f;
            for (int jp = 0; jp < r; ++jp)
                u += sC[m + j][m + jp] * sS[m + jp][i];
            accq2 += aij * u;
        }
#pragma unroll
        for (int o = 16; o > 0; o >>= 1) {
            accv  += __shfl_xor_sync(0xffffffffu, accv,  o);
            accq1 += __shfl_xor_sync(0xffffffffu, accq1, o);
            accq2 += __shfl_xor_sync(0xffffffffu, accq2, o);
        }
        if (lane == 0) {
            float v = sS[i][i] - accv;
            float Q = sC[i][i] - 2.f * accq1 + accq2;
            wsum += -0.5f * logf(v) - 0.5f * LOG2PI_F
                    - 0.5f * Q / (v * (float)N_);
        }
    }
    if (lane == 0) swsum[wid] = wsum;
    __syncthreads();
    if (tid == 0) {
        float s = 0.f;
#pragma unroll
        for (int w = 0; w < 8; ++w) s += swsum[w];
        atomicAdd(&g_loss, (double)s / ((double)P_ * (double)m));
    }
}

// ---------------------------------------------------------------------------
// Kernel 3: write scalar output = -total
// ---------------------------------------------------------------------------
__global__ void k_out(float* out) {
    out[0] = -(float)g_loss;
}

extern "C" void kernel_launch(void* const* d_in, const int* in_sizes, int n_in,
                              void* d_out, int out_size) {
    const float* x     = (const float*)d_in[0];
    const float* W     = (const float*)d_in[1];
    const int*   perms = (const int*)d_in[2];
    (void)in_sizes; (void)n_in; (void)out_size;

    k_zero<<<16, 256>>>();
    k_xtx<<<XTX_BLOCKS, 256>>>(x);
    k_pairs<<<D_ * P_, 256>>>(W, perms);
    k_out<<<1, 1>>>((float*)d_out);
}

// round 2
// speedup vs baseline: 1.8545x; 1.8545x over previous
#include <cuda_runtime.h>

#define D_      64
#define K_      16
#define N_      65536
#define P_      2
#define NOISEF  0.1f
#define LOG2PI_F 1.83787706640934534f

__device__ double g_C[D_ * D_];
__device__ double g_loss;

typedef unsigned long long u64;

__device__ __forceinline__ void ffma2(u64& acc, u64 a, u64 b) {
    asm("fma.rn.f32x2 %0, %1, %2, %3;" : "=l"(acc) : "l"(a), "l"(b), "l"(acc));
}
__device__ __forceinline__ u64 dup2(float v) {
    u64 r;
    asm("mov.b64 %0, {%1, %1};" : "=l"(r) : "f"(v));
    return r;
}

// ---------------------------------------------------------------------------
// Kernel 1: C = x^T x via packed f32x2 FMA. 256 blocks x 256 threads,
// 256 rows/block staged 64 at a time in shared. 4 groups of 64 threads,
// each thread an 8x8 register tile (stored as 8x4 packed f32x2 pairs).
// ---------------------------------------------------------------------------
#define XTX_BLOCKS 256
__global__ __launch_bounds__(256, 2) void k_xtx(const float* __restrict__ x) {
    __shared__ float sx[64 * 64];
    const int tid = threadIdx.x;
    const int g   = tid >> 6;
    const int t   = tid & 63;
    const int ti  = (t >> 3) << 3;
    const int tj  = (t & 7) << 3;

    u64 acc2[8][4];
#pragma unroll
    for (int u = 0; u < 8; ++u)
#pragma unroll
        for (int v = 0; v < 4; ++v) acc2[u][v] = 0ull;

    const int rows_per_block = N_ / XTX_BLOCKS;  // 256
    const long long base = (long long)blockIdx.x * rows_per_block * D_;

    for (int it = 0; it < rows_per_block; it += 64) {
        const float4* src4 = reinterpret_cast<const float4*>(x + base + (long long)it * D_);
        float4* dst4 = reinterpret_cast<float4*>(sx);
#pragma unroll
        for (int i = 0; i < 4; ++i) dst4[tid + 256 * i] = src4[tid + 256 * i];
        __syncthreads();

        const float* rb = sx + g * (16 * 64);
#pragma unroll
        for (int rr = 0; rr < 16; ++rr) {
            const float4* xiv = reinterpret_cast<const float4*>(rb + rr * 64 + ti);
            float4 a0 = xiv[0], a1 = xiv[1];
            u64 xi2[8];
            xi2[0] = dup2(a0.x); xi2[1] = dup2(a0.y);
            xi2[2] = dup2(a0.z); xi2[3] = dup2(a0.w);
            xi2[4] = dup2(a1.x); xi2[5] = dup2(a1.y);
            xi2[6] = dup2(a1.z); xi2[7] = dup2(a1.w);
            const u64* xjv = reinterpret_cast<const u64*>(rb + rr * 64 + tj);
            u64 xj2[4];
#pragma unroll
            for (int v = 0; v < 4; ++v) xj2[v] = xjv[v];
#pragma unroll
            for (int u = 0; u < 8; ++u)
#pragma unroll
                for (int v = 0; v < 4; ++v) ffma2(acc2[u][v], xi2[u], xj2[v]);
        }
        __syncthreads();
    }

    // Reduce 4 groups into sx
    for (int gg = 0; gg < 4; ++gg) {
        if (g == gg) {
#pragma unroll
            for (int u = 0; u < 8; ++u)
#pragma unroll
                for (int v = 0; v < 4; ++v) {
                    float lo = __uint_as_float((unsigned)(acc2[u][v] & 0xffffffffull));
                    float hi = __uint_as_float((unsigned)(acc2[u][v] >> 32));
                    int idx = (ti + u) * 64 + tj + 2 * v;
                    if (gg == 0) { sx[idx] = lo; sx[idx + 1] = hi; }
                    else         { sx[idx] += lo; sx[idx + 1] += hi; }
                }
        }
        __syncthreads();
    }

    for (int i = tid; i < 4096; i += 256)
        atomicAdd(&g_C[i], (double)sx[i]);
}

// ---------------------------------------------------------------------------
// Kernel 2: one block per (a,p). Woodbury formulation:
//   G = 0.1 I16 + W_r^T W_r          (16x16)
//   Y = Cp[:, m:] @ W_r              (64x16)   (Y_i = W_r^T Cp[m:, i], C symm)
//   T = W_r^T C_rr W_r = sum_{i>=m} W_p[i] (x) Y[i]
//   b_i = Ginv w_i
//   v_i = 0.1 (1 + w_i . b_i)
//   Q_i = Cp_ii - 2 b_i.Y_i + b_i^T T b_i
//   term_i = -.5 log v_i - .5 log2pi - .5 Q_i/(v_i N)
// ---------------------------------------------------------------------------
__global__ __launch_bounds__(256) void k_pairs(const float* __restrict__ W,
                                               const int* __restrict__ perms) {
    __shared__ float sC[D_][D_ + 1];
    __shared__ float sW[D_][K_ + 1];
    __shared__ float sY[D_][K_ + 1];
    __shared__ float sT[K_][K_ + 1];
    __shared__ float sG[K_][2 * K_ + 1];
    __shared__ float sGi[K_][K_ + 1];
    __shared__ float smult[K_];
    __shared__ int   sperm[D_];
    __shared__ float sred[2];

    const int tid = threadIdx.x;
    const int a   = blockIdx.x >> 1;
    const int p   = blockIdx.x & 1;
    const int m   = a + 1;
    const int* perm = perms + (a * P_ + p) * D_;

    if (tid < D_) sperm[tid] = perm[tid];
    __syncthreads();

    for (int i = tid; i < D_ * K_; i += 256) {
        int row = i >> 4, c = i & 15;
        sW[row][c] = W[sperm[row] * K_ + c];
    }
    for (int i = tid; i < D_ * D_; i += 256) {
        int row = i >> 6, c = i & 63;
        sC[row][c] = (float)g_C[sperm[row] * D_ + sperm[c]];
    }
    __syncthreads();

    // G (one element per thread) + augmented identity
    {
        int k = tid >> 4, l = tid & 15;
        float s = (k == l) ? NOISEF : 0.f;
        for (int i = m; i < D_; ++i) s += sW[i][k] * sW[i][l];
        sG[k][l] = s;
        sG[k][K_ + l] = (k == l) ? 1.f : 0.f;
    }
    // Y: i = tid&63, 4 k-values per thread
    {
        int i = tid & 63, kb = (tid >> 6) << 2;
        float y0 = 0.f, y1 = 0.f, y2 = 0.f, y3 = 0.f;
        for (int j = m; j < D_; ++j) {
            float c = sC[i][j];
            y0 += c * sW[j][kb];
            y1 += c * sW[j][kb + 1];
            y2 += c * sW[j][kb + 2];
            y3 += c * sW[j][kb + 3];
        }
        sY[i][kb] = y0; sY[i][kb + 1] = y1; sY[i][kb + 2] = y2; sY[i][kb + 3] = y3;
    }
    __syncthreads();

    // T (one element per thread)
    {
        int k = tid >> 4, l = tid & 15;
        float s = 0.f;
        for (int i = m; i < D_; ++i) s += sW[i][k] * sY[i][l];
        sT[k][l] = s;
    }
    // Jordan inversion of G (16 steps, no pivoting: G is SPD with diag >= 0.1)
    for (int k = 0; k < K_; ++k) {
        if (tid < K_ && tid != k) smult[tid] = sG[tid][k] / sG[k][k];
        __syncthreads();
        for (int i = tid; i < K_ * 2 * K_; i += 256) {
            int row = i >> 5, c = i & 31;
            if (row != k) sG[row][c] -= smult[row] * sG[k][c];
        }
        __syncthreads();
    }
    {
        int k = tid >> 4, l = tid & 15;
        sGi[k][l] = sG[k][K_ + l] / sG[k][k];
    }
    __syncthreads();

    // Per-i terms: thread i < m handles row i
    float term = 0.f;
    if (tid < m) {
        const int i = tid;
        float w[K_], b[K_];
#pragma unroll
        for (int k = 0; k < K_; ++k) w[k] = sW[i][k];
#pragma unroll
        for (int l = 0; l < K_; ++l) {
            float s = 0.f;
#pragma unroll
            for (int k = 0; k < K_; ++k) s += sGi[l][k] * w[k];
            b[l] = s;
        }
        float wb = 0.f, by = 0.f, btb = 0.f;
#pragma unroll
        for (int k = 0; k < K_; ++k) {
            wb += w[k] * b[k];
            by += b[k] * sY[i][k];
            float s = 0.f;
#pragma unroll
            for (int l = 0; l < K_; ++l) s += sT[k][l] * b[l];
            btb += b[k] * s;
        }
        float v = NOISEF * (1.f + wb);
        float Q = sC[i][i] - 2.f * by + btb;
        term = -0.5f * logf(v) - 0.5f * LOG2PI_F - 0.5f * Q / (v * (float)N_);
    }
    if (tid < 64) {
#pragma unroll
        for (int o = 16; o > 0; o >>= 1)
            term += __shfl_xor_sync(0xffffffffu, term, o);
        if ((tid & 31) == 0) sred[tid >> 5] = term;
    }
    __syncthreads();
    if (tid == 0)
        atomicAdd(&g_loss, (double)(sred[0] + sred[1]) / ((double)P_ * (double)m));
}

// ---------------------------------------------------------------------------
// Kernel 3: write output, then reset accumulators for the next call
// (state is zero-initialized at load; every call leaves it zeroed).
// ---------------------------------------------------------------------------
__global__ void k_out(float* out) {
    int i = blockIdx.x * blockDim.x + threadIdx.x;
    if (i < D_ * D_) g_C[i] = 0.0;
    if (i == 0) {
        out[0] = -(float)g_loss;
        g_loss = 0.0;
    }
}

extern "C" void kernel_launch(void* const* d_in, const int* in_sizes, int n_in,
                              void* d_out, int out_size) {
    const float* x     = (const float*)d_in[0];
    const float* W     = (const float*)d_in[1];
    const int*   perms = (const int*)d_in[2];
    (void)in_sizes; (void)n_in; (void)out_size;

    k_xtx<<<XTX_BLOCKS, 256>>>(x);
    k_pairs<<<D_ * P_, 256>>>(W, perms);
    k_out<<<16, 256>>>((float*)d_out);
}